// round 2
// baseline (speedup 1.0000x reference)
#include <cuda_runtime.h>
#include <math.h>

#define NN   50000
#define NE   800000
#define ET   (NE + NN)        // 850000 edges incl. self loops
#define IND  64
#define HID  192
#define NH   12
#define CD   16
#define NL   3
#define EPSF 1e-5f
#define TM   16               // nodes per GEMM tile block

// ---------------- scratch (static device globals; no allocation) ----------------
__device__ float d_h   [NN * HID];
__device__ float d_xl  [NN * HID];
__device__ float d_xr  [NN * HID];
__device__ float d_tmp [NN * HID];     // conv numerator / pre-LN temp
__device__ float d_s   [(size_t)ET * NH];
__device__ float d_smax[NN * NH];
__device__ float d_den [NN * NH];
__device__ float d_cnt [NN];
__device__ float d_suma[NN * 2];
__device__ float d_ma  [NN * 2];

// ---------------- helpers ----------------
__device__ __forceinline__ void atomicMaxF(float* addr, float v) {
    if (v >= 0.f) atomicMax((int*)addr, __float_as_int(v));
    else          atomicMin((unsigned int*)addr, __float_as_uint(v));
}

// block-wide mean/rstd over 192 values (6 warps)
__device__ __forceinline__ void blockStats192(float v, float& mean, float& rstd) {
    __shared__ float red[14];
    float s = v, s2 = v * v;
    #pragma unroll
    for (int o = 16; o; o >>= 1) {
        s  += __shfl_xor_sync(0xffffffffu, s,  o);
        s2 += __shfl_xor_sync(0xffffffffu, s2, o);
    }
    int w = threadIdx.x >> 5;
    if ((threadIdx.x & 31) == 0) { red[w] = s; red[7 + w] = s2; }
    __syncthreads();
    if (threadIdx.x == 0) {
        float ts = 0.f, t2 = 0.f;
        #pragma unroll
        for (int i = 0; i < 6; i++) { ts += red[i]; t2 += red[7 + i]; }
        float m   = ts * (1.f / HID);
        float var = t2 * (1.f / HID) - m * m;
        red[6]  = m;
        red[13] = rsqrtf(var + EPSF);
    }
    __syncthreads();
    mean = red[6];
    rstd = red[13];
}

// ---------------- fills ----------------
__global__ void k_fill(float* p, float v, int n) {
    int i = blockIdx.x * blockDim.x + threadIdx.x;
    if (i < n) p[i] = v;
}

// per-layer clear: d_den=0, d_smax=-inf, d_tmp=0 in one launch
__global__ void k_clear() {
    int i = blockIdx.x * blockDim.x + threadIdx.x;
    if (i < NN * NH) { d_den[i] = 0.f; d_smax[i] = -INFINITY; }
    if (i < NN * HID) d_tmp[i] = 0.f;
}

// ---------------- self-loop mean edge_attr ----------------
__global__ void k_count(const int* __restrict__ ei, const float* __restrict__ eattr) {
    int e = blockIdx.x * blockDim.x + threadIdx.x;
    if (e >= NE) return;
    int dst = ei[NE + e];
    atomicAdd(&d_cnt[dst], 1.f);
    atomicAdd(&d_suma[2 * dst    ], eattr[2 * e    ]);
    atomicAdd(&d_suma[2 * dst + 1], eattr[2 * e + 1]);
}

__global__ void k_mean() {
    int n = blockIdx.x * blockDim.x + threadIdx.x;
    if (n >= NN) return;
    float c = fmaxf(d_cnt[n], 1.f);
    d_ma[2 * n    ] = d_suma[2 * n    ] / c;
    d_ma[2 * n + 1] = d_suma[2 * n + 1] / c;
}

// ---------------- input projection: x@W_in + b, GELU -> d_tmp ----------------
__global__ void k_inproj(const float* __restrict__ x, const float* __restrict__ W,
                         const float* __restrict__ b) {
    __shared__ float sx[TM * IND];
    int base = blockIdx.x * TM;
    int j = threadIdx.x;                 // 192 threads = output col
    for (int i = j; i < TM * IND; i += HID) sx[i] = x[(size_t)base * IND + i];
    __syncthreads();
    float acc[TM];
    #pragma unroll
    for (int m = 0; m < TM; m++) acc[m] = b[j];
    for (int k = 0; k < IND; k++) {
        float w = W[k * HID + j];
        #pragma unroll
        for (int m = 0; m < TM; m++) acc[m] = fmaf(sx[m * IND + k], w, acc[m]);
    }
    #pragma unroll
    for (int m = 0; m < TM; m++) {
        float v = acc[m];
        d_tmp[(size_t)(base + m) * HID + j] = v * normcdff(v);   // exact GELU
    }
}

// ---------------- LayerNorm: out = LN(in)*g + b ----------------
__global__ void k_ln(const float* __restrict__ in, const float* __restrict__ g,
                     const float* __restrict__ b, float* __restrict__ out) {
    int n = blockIdx.x, j = threadIdx.x;
    float v = in[(size_t)n * HID + j];
    float m, r; blockStats192(v, m, r);
    out[(size_t)n * HID + j] = (v - m) * r * g[j] + b[j];
}

// ---------------- per-layer dual GEMM: xl = h@Wl+bl, xr = h@Wr+br ----------------
__global__ void k_gemm2(const float* __restrict__ Wl, const float* __restrict__ bl,
                        const float* __restrict__ Wr, const float* __restrict__ br) {
    __shared__ float sh[TM * HID];
    int base = blockIdx.x * TM;
    int j = threadIdx.x;
    for (int i = j; i < TM * HID; i += HID) sh[i] = d_h[(size_t)base * HID + i];
    __syncthreads();
    float al[TM], ar[TM];
    #pragma unroll
    for (int m = 0; m < TM; m++) { al[m] = bl[j]; ar[m] = br[j]; }
    for (int k = 0; k < HID; k++) {
        float wl = Wl[k * HID + j];
        float wr = Wr[k * HID + j];
        #pragma unroll
        for (int m = 0; m < TM; m++) {
            float hv = sh[m * HID + k];
            al[m] = fmaf(hv, wl, al[m]);
            ar[m] = fmaf(hv, wr, ar[m]);
        }
    }
    #pragma unroll
    for (int m = 0; m < TM; m++) {
        d_xl[(size_t)(base + m) * HID + j] = al[m];
        d_xr[(size_t)(base + m) * HID + j] = ar[m];
    }
}

// ---------------- edge pass A: scores + segment max ----------------
__global__ void k_edgeA(const int* __restrict__ ei, const float* __restrict__ eattr,
                        const float* __restrict__ We, const float* __restrict__ att) {
    __shared__ float sWe0[HID], sWe1[HID], sAtt[HID];
    for (int i = threadIdx.x; i < HID; i += blockDim.x) {
        sWe0[i] = We[i]; sWe1[i] = We[HID + i]; sAtt[i] = att[i];
    }
    __syncthreads();
    int t = blockIdx.x * blockDim.x + threadIdx.x;
    if (t >= ET * NH) return;
    int e = t / NH, hh = t - e * NH;
    int src, dst; float ea0, ea1;
    if (e < NE) {
        src = ei[e]; dst = ei[NE + e];
        ea0 = eattr[2 * e]; ea1 = eattr[2 * e + 1];
    } else {
        src = dst = e - NE;
        ea0 = d_ma[2 * src]; ea1 = d_ma[2 * src + 1];
    }
    const float4* pl = (const float4*)&d_xl[(size_t)src * HID + hh * CD];
    const float4* pr = (const float4*)&d_xr[(size_t)dst * HID + hh * CD];
    float s = 0.f;
    #pragma unroll
    for (int i = 0; i < 4; i++) {
        float4 a = pl[i], bq = pr[i];
        int jb = hh * CD + i * 4;
        float m0 = a.x + bq.x + ea0 * sWe0[jb + 0] + ea1 * sWe1[jb + 0];
        float m1 = a.y + bq.y + ea0 * sWe0[jb + 1] + ea1 * sWe1[jb + 1];
        float m2 = a.z + bq.z + ea0 * sWe0[jb + 2] + ea1 * sWe1[jb + 2];
        float m3 = a.w + bq.w + ea0 * sWe0[jb + 3] + ea1 * sWe1[jb + 3];
        m0 = m0 > 0.f ? m0 : 0.2f * m0;
        m1 = m1 > 0.f ? m1 : 0.2f * m1;
        m2 = m2 > 0.f ? m2 : 0.2f * m2;
        m3 = m3 > 0.f ? m3 : 0.2f * m3;
        s += m0 * sAtt[jb + 0] + m1 * sAtt[jb + 1] + m2 * sAtt[jb + 2] + m3 * sAtt[jb + 3];
    }
    d_s[(size_t)e * NH + hh] = s;
    atomicMaxF(&d_smax[dst * NH + hh], s);
}

// ---------------- edge pass B: exp, denominator, weighted aggregate ----------------
__global__ void k_edgeB(const int* __restrict__ ei) {
    int t = blockIdx.x * blockDim.x + threadIdx.x;
    if (t >= ET * NH) return;
    int e = t / NH, hh = t - e * NH;
    int src, dst;
    if (e < NE) { src = ei[e]; dst = ei[NE + e]; }
    else        { src = dst = e - NE; }
    float ex = __expf(d_s[(size_t)e * NH + hh] - d_smax[dst * NH + hh]);
    atomicAdd(&d_den[dst * NH + hh], ex);
    const float4* pl = (const float4*)&d_xl[(size_t)src * HID + hh * CD];
    float4* po = (float4*)&d_tmp[(size_t)dst * HID + hh * CD];
    #pragma unroll
    for (int i = 0; i < 4; i++) {
        float4 a = pl[i];
        float4 v = make_float4(ex * a.x, ex * a.y, ex * a.z, ex * a.w);
        atomicAdd(&po[i], v);       // sm_90+ vector RED
    }
}

// ---------------- residual + LN ----------------
__global__ void k_resln(const float* __restrict__ bo, const float* __restrict__ g,
                        const float* __restrict__ b) {
    int n = blockIdx.x, j = threadIdx.x;
    float den = d_den[n * NH + (j >> 4)];
    float v = d_h[(size_t)n * HID + j] + d_tmp[(size_t)n * HID + j] / den + bo[j];
    float m, r; blockStats192(v, m, r);
    d_h[(size_t)n * HID + j] = (v - m) * r * g[j] + b[j];
}

// ---------------- gate: d_tmp = h * sigmoid(h@Wg + bg) ----------------
__global__ void k_gate(const float* __restrict__ Wg, const float* __restrict__ bg) {
    __shared__ float sh[TM * HID];
    int base = blockIdx.x * TM;
    int j = threadIdx.x;
    for (int i = j; i < TM * HID; i += HID) sh[i] = d_h[(size_t)base * HID + i];
    __syncthreads();
    float acc[TM];
    #pragma unroll
    for (int m = 0; m < TM; m++) acc[m] = bg[j];
    for (int k = 0; k < HID; k++) {
        float w = Wg[k * HID + j];
        #pragma unroll
        for (int m = 0; m < TM; m++) acc[m] = fmaf(sh[m * HID + k], w, acc[m]);
    }
    #pragma unroll
    for (int m = 0; m < TM; m++) {
        float gsig = 1.f / (1.f + __expf(-acc[m]));
        d_tmp[(size_t)(base + m) * HID + j] = sh[m * HID + j] * gsig;
    }
}

// ---------------- launcher ----------------
extern "C" void kernel_launch(void* const* d_in, const int* in_sizes, int n_in,
                              void* d_out, int out_size) {
    const float* x     = (const float*)d_in[0];
    const int*   ei    = (const int*)  d_in[1];
    const float* eattr = (const float*)d_in[2];
    const float* Win   = (const float*)d_in[3];
    const float* b_in  = (const float*)d_in[4];
    const float* g_lni = (const float*)d_in[5];
    const float* b_lni = (const float*)d_in[6];
    const float* Wl    = (const float*)d_in[7];
    const float* bl    = (const float*)d_in[8];
    const float* Wr    = (const float*)d_in[9];
    const float* br    = (const float*)d_in[10];
    const float* We    = (const float*)d_in[11];
    const float* att   = (const float*)d_in[12];
    const float* bo    = (const float*)d_in[13];
    const float* g_res = (const float*)d_in[14];
    const float* b_res = (const float*)d_in[15];
    const float* Wg    = (const float*)d_in[16];
    const float* bg    = (const float*)d_in[17];
    const float* g_f   = (const float*)d_in[18];
    const float* b_f   = (const float*)d_in[19];
    float* out = (float*)d_out;

    float *p_tmp, *p_h, *p_cnt, *p_suma;
    cudaGetSymbolAddress((void**)&p_tmp,  d_tmp);
    cudaGetSymbolAddress((void**)&p_h,    d_h);
    cudaGetSymbolAddress((void**)&p_cnt,  d_cnt);
    cudaGetSymbolAddress((void**)&p_suma, d_suma);

    const int GB = NN / TM;                 // 3125 GEMM tile blocks
    const int EG = (ET * NH + 255) / 256;   // edge-kernel grid

    // self-loop mean edge_attr
    k_fill<<<(NN + 255) / 256, 256>>>(p_cnt, 0.f, NN);
    k_fill<<<(2 * NN + 255) / 256, 256>>>(p_suma, 0.f, 2 * NN);
    k_count<<<(NE + 255) / 256, 256>>>(ei, eattr);
    k_mean<<<(NN + 255) / 256, 256>>>();

    // input projection + GELU + LN -> d_h
    k_inproj<<<GB, HID>>>(x, Win, b_in);
    k_ln<<<NN, HID>>>(p_tmp, g_lni, b_lni, p_h);

    for (int l = 0; l < NL; l++) {
        k_clear<<<(NN * HID + 255) / 256, 256>>>();
        k_gemm2<<<GB, HID>>>(Wl + (size_t)l * HID * HID, bl + l * HID,
                             Wr + (size_t)l * HID * HID, br + l * HID);
        k_edgeA<<<EG, 256>>>(ei, eattr, We + (size_t)l * 2 * HID, att + (size_t)l * HID);
        k_edgeB<<<EG, 256>>>(ei);
        k_resln<<<NN, HID>>>(bo + l * HID, g_res + l * HID, b_res + l * HID);
    }

    k_gate<<<GB, HID>>>(Wg, bg);
    k_ln<<<NN, HID>>>(p_tmp, g_f, b_f, out);
}

// round 3
// speedup vs baseline: 1.5048x; 1.5048x over previous
#include <cuda_runtime.h>
#include <math.h>

#define NN   50000
#define NE   800000
#define IND  64
#define HID  192
#define NH   12
#define CD   16
#define NL   3
#define EPSF 1e-5f
#define TM   16               // nodes per GEMM tile block

// ---------------- scratch (static device globals; no allocation) ----------------
__device__ float  d_h   [NN * HID];
__device__ float  d_xl  [NN * HID];
__device__ float  d_xr  [NN * HID];
__device__ float  d_tmp [NN * HID];     // inproj / gate temp
__device__ int    d_deg [NN];
__device__ int    d_fill[NN];
__device__ int    d_rows[NN + 1];
__device__ int    d_csrc[NE];
__device__ float2 d_cea [NE];
__device__ float  d_suma[NN * 2];
__device__ float  d_ma  [NN * 2];

// block-wide mean/rstd over 192 values (6 warps)
__device__ __forceinline__ void blockStats192(float v, float& mean, float& rstd) {
    __shared__ float red[14];
    float s = v, s2 = v * v;
    #pragma unroll
    for (int o = 16; o; o >>= 1) {
        s  += __shfl_xor_sync(0xffffffffu, s,  o);
        s2 += __shfl_xor_sync(0xffffffffu, s2, o);
    }
    int w = threadIdx.x >> 5;
    if ((threadIdx.x & 31) == 0) { red[w] = s; red[7 + w] = s2; }
    __syncthreads();
    if (threadIdx.x == 0) {
        float ts = 0.f, t2 = 0.f;
        #pragma unroll
        for (int i = 0; i < 6; i++) { ts += red[i]; t2 += red[7 + i]; }
        float m   = ts * (1.f / HID);
        float var = t2 * (1.f / HID) - m * m;
        red[6]  = m;
        red[13] = rsqrtf(var + EPSF);
    }
    __syncthreads();
    mean = red[6];
    rstd = red[13];
}

// ---------------- CSR build ----------------
__global__ void k_zero() {
    int i = blockIdx.x * blockDim.x + threadIdx.x;
    if (i < NN) { d_deg[i] = 0; d_fill[i] = 0; }
    if (i < 2 * NN) d_suma[i] = 0.f;
}

__global__ void k_hist(const int* __restrict__ ei, const float* __restrict__ eattr) {
    int e = blockIdx.x * blockDim.x + threadIdx.x;
    if (e >= NE) return;
    int dst = ei[NE + e];
    atomicAdd(&d_deg[dst], 1);
    atomicAdd(&d_suma[2 * dst    ], eattr[2 * e    ]);
    atomicAdd(&d_suma[2 * dst + 1], eattr[2 * e + 1]);
}

__global__ void k_mean() {
    int n = blockIdx.x * blockDim.x + threadIdx.x;
    if (n >= NN) return;
    float c = fmaxf((float)d_deg[n], 1.f);
    d_ma[2 * n    ] = d_suma[2 * n    ] / c;
    d_ma[2 * n + 1] = d_suma[2 * n + 1] / c;
}

// single-block exclusive scan of d_deg -> d_rows (1024 threads)
__global__ void k_scan() {
    __shared__ int wsum[32];
    __shared__ int s_off;
    int t = threadIdx.x, lane = t & 31, w = t >> 5;
    if (t == 0) { s_off = 0; d_rows[0] = 0; }
    __syncthreads();
    for (int base = 0; base < NN; base += 1024) {
        int v = (base + t < NN) ? d_deg[base + t] : 0;
        int sv = v;
        #pragma unroll
        for (int o = 1; o < 32; o <<= 1) {
            int u = __shfl_up_sync(0xffffffffu, sv, o);
            if (lane >= o) sv += u;
        }
        if (lane == 31) wsum[w] = sv;
        __syncthreads();
        if (w == 0) {
            int x = wsum[lane];
            #pragma unroll
            for (int o = 1; o < 32; o <<= 1) {
                int u = __shfl_up_sync(0xffffffffu, x, o);
                if (lane >= o) x += u;
            }
            wsum[lane] = x;
        }
        __syncthreads();
        int blocksum = wsum[31];
        int add = (w > 0) ? wsum[w - 1] : 0;
        int off = s_off;
        if (base + t < NN) d_rows[base + t + 1] = off + add + sv;
        __syncthreads();
        if (t == 0) s_off = off + blocksum;
        __syncthreads();
    }
}

__global__ void k_scatter(const int* __restrict__ ei, const float* __restrict__ eattr) {
    int e = blockIdx.x * blockDim.x + threadIdx.x;
    if (e >= NE) return;
    int dst = ei[NE + e];
    int pos = d_rows[dst] + atomicAdd(&d_fill[dst], 1);
    d_csrc[pos] = ei[e];
    d_cea[pos]  = make_float2(eattr[2 * e], eattr[2 * e + 1]);
}

// ---------------- input projection: x@W_in + b, GELU -> d_tmp ----------------
__global__ void k_inproj(const float* __restrict__ x, const float* __restrict__ W,
                         const float* __restrict__ b) {
    __shared__ float sx[TM * IND];
    int base = blockIdx.x * TM;
    int j = threadIdx.x;
    for (int i = j; i < TM * IND; i += HID) sx[i] = x[(size_t)base * IND + i];
    __syncthreads();
    float acc[TM];
    #pragma unroll
    for (int m = 0; m < TM; m++) acc[m] = b[j];
    for (int k = 0; k < IND; k++) {
        float w = W[k * HID + j];
        #pragma unroll
        for (int m = 0; m < TM; m++) acc[m] = fmaf(sx[m * IND + k], w, acc[m]);
    }
    #pragma unroll
    for (int m = 0; m < TM; m++) {
        float v = acc[m];
        d_tmp[(size_t)(base + m) * HID + j] = v * normcdff(v);   // exact GELU
    }
}

// ---------------- LayerNorm: out = LN(in)*g + b ----------------
__global__ void k_ln(const float* __restrict__ in, const float* __restrict__ g,
                     const float* __restrict__ b, float* __restrict__ out) {
    int n = blockIdx.x, j = threadIdx.x;
    float v = in[(size_t)n * HID + j];
    float m, r; blockStats192(v, m, r);
    out[(size_t)n * HID + j] = (v - m) * r * g[j] + b[j];
}

// ---------------- per-layer dual GEMM: xl = h@Wl+bl, xr = h@Wr+br ----------------
__global__ void k_gemm2(const float* __restrict__ Wl, const float* __restrict__ bl,
                        const float* __restrict__ Wr, const float* __restrict__ br) {
    __shared__ float sh[TM * HID];
    int base = blockIdx.x * TM;
    int j = threadIdx.x;
    for (int i = j; i < TM * HID; i += HID) sh[i] = d_h[(size_t)base * HID + i];
    __syncthreads();
    float al[TM], ar[TM];
    #pragma unroll
    for (int m = 0; m < TM; m++) { al[m] = bl[j]; ar[m] = br[j]; }
    for (int k = 0; k < HID; k++) {
        float wl = Wl[k * HID + j];
        float wr = Wr[k * HID + j];
        #pragma unroll
        for (int m = 0; m < TM; m++) {
            float hv = sh[m * HID + k];
            al[m] = fmaf(hv, wl, al[m]);
            ar[m] = fmaf(hv, wr, ar[m]);
        }
    }
    #pragma unroll
    for (int m = 0; m < TM; m++) {
        d_xl[(size_t)(base + m) * HID + j] = al[m];
        d_xr[(size_t)(base + m) * HID + j] = ar[m];
    }
}

// ---------------- fused per-node edge pass: online softmax + aggregate + residual + LN ----------------
__global__ void k_node(const float* __restrict__ We, const float* __restrict__ att,
                       const float* __restrict__ bo, const float* __restrict__ g,
                       const float* __restrict__ b) {
    __shared__ float sW0[HID], sW1[HID], sA[HID];
    int n = blockIdx.x, j = threadIdx.x;
    sW0[j] = We[j]; sW1[j] = We[HID + j]; sA[j] = att[j];
    __syncthreads();
    float w0 = sW0[j], w1 = sW1[j], aj = sA[j];
    float xr_j = d_xr[(size_t)n * HID + j];

    // self-loop initializes the online softmax state
    float ea0 = d_ma[2 * n], ea1 = d_ma[2 * n + 1];
    float xl_self = d_xl[(size_t)n * HID + j];
    float m0 = xl_self + xr_j + ea0 * w0 + ea1 * w1;
    m0 = m0 > 0.f ? m0 : 0.2f * m0;
    float t0 = m0 * aj;
    #pragma unroll
    for (int o = 8; o; o >>= 1) t0 += __shfl_xor_sync(0xffffffffu, t0, o);
    float run_m = t0, den = 1.f, acc = xl_self;

    int p = d_rows[n], pe = d_rows[n + 1];
    int    src_n = 0;
    float2 ea_n  = make_float2(0.f, 0.f);
    float  xl_n  = 0.f;
    if (p < pe) {
        src_n = d_csrc[p];
        ea_n  = d_cea[p];
        xl_n  = d_xl[(size_t)src_n * HID + j];
    }
    while (p < pe) {
        float2 ea = ea_n;
        float  xl = xl_n;
        ++p;
        if (p < pe) {                       // prefetch next edge
            src_n = d_csrc[p];
            ea_n  = d_cea[p];
            xl_n  = d_xl[(size_t)src_n * HID + j];
        }
        float mm = xl + xr_j + ea.x * w0 + ea.y * w1;
        mm = mm > 0.f ? mm : 0.2f * mm;
        float tt = mm * aj;
        #pragma unroll
        for (int o = 8; o; o >>= 1) tt += __shfl_xor_sync(0xffffffffu, tt, o);
        float nm = fmaxf(run_m, tt);
        float sc = __expf(run_m - nm);
        float ex = __expf(tt - nm);
        den = den * sc + ex;
        acc = acc * sc + ex * xl;
        run_m = nm;
    }

    float v = d_h[(size_t)n * HID + j] + acc / den + bo[j];
    float mean, rstd; blockStats192(v, mean, rstd);
    d_h[(size_t)n * HID + j] = (v - mean) * rstd * g[j] + b[j];
}

// ---------------- gate: d_tmp = h * sigmoid(h@Wg + bg) ----------------
__global__ void k_gate(const float* __restrict__ Wg, const float* __restrict__ bg) {
    __shared__ float sh[TM * HID];
    int base = blockIdx.x * TM;
    int j = threadIdx.x;
    for (int i = j; i < TM * HID; i += HID) sh[i] = d_h[(size_t)base * HID + i];
    __syncthreads();
    float acc[TM];
    #pragma unroll
    for (int m = 0; m < TM; m++) acc[m] = bg[j];
    for (int k = 0; k < HID; k++) {
        float w = Wg[k * HID + j];
        #pragma unroll
        for (int m = 0; m < TM; m++) acc[m] = fmaf(sh[m * HID + k], w, acc[m]);
    }
    #pragma unroll
    for (int m = 0; m < TM; m++) {
        float gsig = 1.f / (1.f + __expf(-acc[m]));
        d_tmp[(size_t)(base + m) * HID + j] = sh[m * HID + j] * gsig;
    }
}

// ---------------- launcher ----------------
extern "C" void kernel_launch(void* const* d_in, const int* in_sizes, int n_in,
                              void* d_out, int out_size) {
    const float* x     = (const float*)d_in[0];
    const int*   ei    = (const int*)  d_in[1];
    const float* eattr = (const float*)d_in[2];
    const float* Win   = (const float*)d_in[3];
    const float* b_in  = (const float*)d_in[4];
    const float* g_lni = (const float*)d_in[5];
    const float* b_lni = (const float*)d_in[6];
    const float* Wl    = (const float*)d_in[7];
    const float* bl    = (const float*)d_in[8];
    const float* Wr    = (const float*)d_in[9];
    const float* br    = (const float*)d_in[10];
    const float* We    = (const float*)d_in[11];
    const float* att   = (const float*)d_in[12];
    const float* bo    = (const float*)d_in[13];
    const float* g_res = (const float*)d_in[14];
    const float* b_res = (const float*)d_in[15];
    const float* Wg    = (const float*)d_in[16];
    const float* bg    = (const float*)d_in[17];
    const float* g_f   = (const float*)d_in[18];
    const float* b_f   = (const float*)d_in[19];
    float* out = (float*)d_out;

    float *p_tmp, *p_h;
    cudaGetSymbolAddress((void**)&p_tmp, d_tmp);
    cudaGetSymbolAddress((void**)&p_h,   d_h);

    const int GB = NN / TM;                 // 3125 GEMM tile blocks

    // CSR build + self-loop mean edge_attr
    k_zero<<<(2 * NN + 255) / 256, 256>>>();
    k_hist<<<(NE + 255) / 256, 256>>>(ei, eattr);
    k_mean<<<(NN + 255) / 256, 256>>>();
    k_scan<<<1, 1024>>>();
    k_scatter<<<(NE + 255) / 256, 256>>>(ei, eattr);

    // input projection + GELU + LN -> d_h
    k_inproj<<<GB, HID>>>(x, Win, b_in);
    k_ln<<<NN, HID>>>(p_tmp, g_lni, b_lni, p_h);

    for (int l = 0; l < NL; l++) {
        k_gemm2<<<GB, HID>>>(Wl + (size_t)l * HID * HID, bl + l * HID,
                             Wr + (size_t)l * HID * HID, br + l * HID);
        k_node<<<NN, HID>>>(We + (size_t)l * 2 * HID, att + (size_t)l * HID,
                            bo + l * HID, g_res + l * HID, b_res + l * HID);
    }

    k_gate<<<GB, HID>>>(Wg, bg);
    k_ln<<<NN, HID>>>(p_tmp, g_f, b_f, out);
}

// round 5
// speedup vs baseline: 1.5519x; 1.0313x over previous
#include <cuda_runtime.h>
#include <math.h>

#define NN   50000
#define NE   800000
#define IND  64
#define HID  192
#define NL   3
#define EPSF 1e-5f
#define TM   16               // nodes per tile (inproj/gate)
#define TG   25               // nodes per tile (gemm2)
#define NB   49               // scan blocks (ceil(NN/1024))

// ---------------- scratch (static device globals; no allocation) ----------------
__device__ float  d_h   [NN * HID];
__device__ float  d_xl  [NN * HID];
__device__ float  d_xr  [NN * HID];
__device__ float  d_tmp [NN * HID];
__device__ int    d_deg [NN];
__device__ int    d_fill[NN];
__device__ int    d_rows[NN + 1];
__device__ int    d_bsum[NB];
__device__ int    d_boff[NB];
__device__ int    d_csrc[NE];
__device__ float2 d_cea [NE];
__device__ float  d_suma[NN * 2];
__device__ float  d_ma  [NN * 2];

// ---------------- f32x2 packed helpers ----------------
typedef unsigned long long u64t;
__device__ __forceinline__ void ffma2(u64t& d, u64t a, u64t b) {
    asm("fma.rn.f32x2 %0, %1, %2, %0;" : "+l"(d) : "l"(a), "l"(b));
}
__device__ __forceinline__ u64t pack2(float lo, float hi) {
    u64t r; asm("mov.b64 %0, {%1, %2};" : "=l"(r) : "f"(lo), "f"(hi)); return r;
}
__device__ __forceinline__ float unpack_sum(u64t v) {
    float lo, hi; asm("mov.b64 {%0, %1}, %2;" : "=f"(lo), "=f"(hi) : "l"(v));
    return lo + hi;
}

// block-wide mean/rstd over 192 values (6 warps)
__device__ __forceinline__ void blockStats192(float v, float& mean, float& rstd) {
    __shared__ float red[14];
    float s = v, s2 = v * v;
    #pragma unroll
    for (int o = 16; o; o >>= 1) {
        s  += __shfl_xor_sync(0xffffffffu, s,  o);
        s2 += __shfl_xor_sync(0xffffffffu, s2, o);
    }
    int w = threadIdx.x >> 5;
    if ((threadIdx.x & 31) == 0) { red[w] = s; red[7 + w] = s2; }
    __syncthreads();
    if (threadIdx.x == 0) {
        float ts = 0.f, t2 = 0.f;
        #pragma unroll
        for (int i = 0; i < 6; i++) { ts += red[i]; t2 += red[7 + i]; }
        float m   = ts * (1.f / HID);
        float var = t2 * (1.f / HID) - m * m;
        red[6]  = m;
        red[13] = rsqrtf(var + EPSF);
    }
    __syncthreads();
    mean = red[6];
    rstd = red[13];
}

// ---------------- CSR build ----------------
__global__ void k_zero() {
    int i = blockIdx.x * blockDim.x + threadIdx.x;
    if (i < NN) { d_deg[i] = 0; d_fill[i] = 0; }
    if (i < 2 * NN) d_suma[i] = 0.f;
}

__global__ void k_hist(const int* __restrict__ ei, const float* __restrict__ eattr) {
    int e = blockIdx.x * blockDim.x + threadIdx.x;
    if (e >= NE) return;
    int dst = ei[NE + e];
    atomicAdd(&d_deg[dst], 1);
    atomicAdd(&d_suma[2 * dst    ], eattr[2 * e    ]);
    atomicAdd(&d_suma[2 * dst + 1], eattr[2 * e + 1]);
}

__global__ void k_mean() {
    int n = blockIdx.x * blockDim.x + threadIdx.x;
    if (n >= NN) return;
    float c = fmaxf((float)d_deg[n], 1.f);
    d_ma[2 * n    ] = d_suma[2 * n    ] / c;
    d_ma[2 * n + 1] = d_suma[2 * n + 1] / c;
}

// scan stage A: per-block inclusive scan of d_deg, block totals to d_bsum
__global__ void k_scanA() {
    __shared__ int wsum[32];
    int i = blockIdx.x * 1024 + threadIdx.x;
    int lane = threadIdx.x & 31, w = threadIdx.x >> 5;
    int v = (i < NN) ? d_deg[i] : 0;
    int sv = v;
    #pragma unroll
    for (int o = 1; o < 32; o <<= 1) {
        int u = __shfl_up_sync(0xffffffffu, sv, o);
        if (lane >= o) sv += u;
    }
    if (lane == 31) wsum[w] = sv;
    __syncthreads();
    if (w == 0) {
        int x = wsum[lane];
        #pragma unroll
        for (int o = 1; o < 32; o <<= 1) {
            int u = __shfl_up_sync(0xffffffffu, x, o);
            if (lane >= o) x += u;
        }
        wsum[lane] = x;
    }
    __syncthreads();
    int add = (w > 0) ? wsum[w - 1] : 0;
    if (i < NN) d_rows[i + 1] = add + sv;
    if (threadIdx.x == 1023) d_bsum[blockIdx.x] = add + sv;
}

// scan stage B: exclusive scan of NB block totals
__global__ void k_scanB() {
    __shared__ int s[NB];
    int t = threadIdx.x;
    if (t < NB) s[t] = d_bsum[t];
    __syncthreads();
    if (t == 0) {
        int run = 0;
        for (int i = 0; i < NB; i++) { int v = s[i]; s[i] = run; run += v; }
    }
    __syncthreads();
    if (t < NB) d_boff[t] = s[t];
}

// scan stage C: add block offsets
__global__ void k_scanC() {
    int i = blockIdx.x * 1024 + threadIdx.x;
    if (i < NN) d_rows[i + 1] += d_boff[blockIdx.x];
    if (i == 0) d_rows[0] = 0;
}

__global__ void k_scatter(const int* __restrict__ ei, const float* __restrict__ eattr) {
    int e = blockIdx.x * blockDim.x + threadIdx.x;
    if (e >= NE) return;
    int dst = ei[NE + e];
    int pos = d_rows[dst] + atomicAdd(&d_fill[dst], 1);
    d_csrc[pos] = ei[e];
    d_cea[pos]  = make_float2(eattr[2 * e], eattr[2 * e + 1]);
}

// ---------------- input projection: x@W_in + b, GELU -> d_tmp ----------------
__global__ void k_inproj(const float* __restrict__ x, const float* __restrict__ W,
                         const float* __restrict__ b) {
    __shared__ float sx[TM * IND];
    int base = blockIdx.x * TM;
    int j = threadIdx.x;
    {
        const float4* src = (const float4*)&x[(size_t)base * IND];
        float4* dstv = (float4*)sx;
        for (int i = j; i < TM * IND / 4; i += HID) dstv[i] = src[i];
    }
    __syncthreads();
    u64t acc2[TM];
    #pragma unroll
    for (int m = 0; m < TM; m++) acc2[m] = 0ull;
    for (int k = 0; k < IND; k += 4) {
        float w0 = W[(k + 0) * HID + j], w1 = W[(k + 1) * HID + j];
        float w2 = W[(k + 2) * HID + j], w3 = W[(k + 3) * HID + j];
        u64t wp01 = pack2(w0, w1), wp23 = pack2(w2, w3);
        #pragma unroll
        for (int m = 0; m < TM; m++) {
            ulonglong2 hp = *(const ulonglong2*)&sx[m * IND + k];
            ffma2(acc2[m], hp.x, wp01);
            ffma2(acc2[m], hp.y, wp23);
        }
    }
    float bj = b[j];
    #pragma unroll
    for (int m = 0; m < TM; m++) {
        float v = unpack_sum(acc2[m]) + bj;
        d_tmp[(size_t)(base + m) * HID + j] = v * normcdff(v);   // exact GELU
    }
}

// ---------------- LayerNorm: out = LN(in)*g + b ----------------
__global__ void k_ln(const float* __restrict__ in, const float* __restrict__ g,
                     const float* __restrict__ b, float* __restrict__ out) {
    int n = blockIdx.x, j = threadIdx.x;
    float v = in[(size_t)n * HID + j];
    float m, r; blockStats192(v, m, r);
    out[(size_t)n * HID + j] = (v - m) * r * g[j] + b[j];
}

// ---------------- dual GEMM: xl = h@Wl+bl, xr = h@Wr+br (f32x2 packed) ----------------
__global__ void k_gemm2(const float* __restrict__ Wl, const float* __restrict__ bl,
                        const float* __restrict__ Wr, const float* __restrict__ br) {
    __shared__ float sh[TG * HID];
    int base = blockIdx.x * TG;
    int j = threadIdx.x;
    {
        const float4* src = (const float4*)&d_h[(size_t)base * HID];
        float4* dstv = (float4*)sh;
        for (int i = j; i < TG * HID / 4; i += HID) dstv[i] = src[i];
    }
    __syncthreads();
    u64t al2[TG], ar2[TG];
    #pragma unroll
    for (int m = 0; m < TG; m++) { al2[m] = 0ull; ar2[m] = 0ull; }
    for (int k = 0; k < HID; k += 4) {
        float wl0 = Wl[(k + 0) * HID + j], wl1 = Wl[(k + 1) * HID + j];
        float wl2 = Wl[(k + 2) * HID + j], wl3 = Wl[(k + 3) * HID + j];
        float wr0 = Wr[(k + 0) * HID + j], wr1 = Wr[(k + 1) * HID + j];
        float wr2 = Wr[(k + 2) * HID + j], wr3 = Wr[(k + 3) * HID + j];
        u64t wlp01 = pack2(wl0, wl1), wlp23 = pack2(wl2, wl3);
        u64t wrp01 = pack2(wr0, wr1), wrp23 = pack2(wr2, wr3);
        #pragma unroll
        for (int m = 0; m < TG; m++) {
            ulonglong2 hp = *(const ulonglong2*)&sh[m * HID + k];
            ffma2(al2[m], hp.x, wlp01);
            ffma2(al2[m], hp.y, wlp23);
            ffma2(ar2[m], hp.x, wrp01);
            ffma2(ar2[m], hp.y, wrp23);
        }
    }
    float blj = bl[j], brj = br[j];
    #pragma unroll
    for (int m = 0; m < TG; m++) {
        d_xl[(size_t)(base + m) * HID + j] = unpack_sum(al2[m]) + blj;
        d_xr[(size_t)(base + m) * HID + j] = unpack_sum(ar2[m]) + brj;
    }
}

// ---------------- fused per-node edge pass (batch-4 online softmax) ----------------
__global__ void k_node(const float* __restrict__ We, const float* __restrict__ att,
                       const float* __restrict__ bo, const float* __restrict__ g,
                       const float* __restrict__ b) {
    __shared__ float sW0[HID], sW1[HID], sA[HID];
    int n = blockIdx.x, j = threadIdx.x;
    sW0[j] = We[j]; sW1[j] = We[HID + j]; sA[j] = att[j];
    __syncthreads();
    float w0 = sW0[j], w1 = sW1[j], aj = sA[j];
    float xr_j = d_xr[(size_t)n * HID + j];

    // self-loop initializes the online softmax state
    float ea0 = d_ma[2 * n], ea1 = d_ma[2 * n + 1];
    float xl_self = d_xl[(size_t)n * HID + j];
    float m0 = xl_self + xr_j + ea0 * w0 + ea1 * w1;
    m0 = m0 > 0.f ? m0 : 0.2f * m0;
    float t0 = m0 * aj;
    #pragma unroll
    for (int o = 8; o; o >>= 1) t0 += __shfl_xor_sync(0xffffffffu, t0, o);
    float run_m = t0, den = 1.f, acc = xl_self;

    int p  = d_rows[n];
    int pe = d_rows[n + 1];

    float  xl_c[4]; float2 ea_c[4];
    int nb_c = min(4, pe - p);
    #pragma unroll
    for (int q = 0; q < 4; q++) {
        if (q < nb_c) {
            int s = d_csrc[p + q];
            ea_c[q] = d_cea[p + q];
            xl_c[q] = d_xl[(size_t)s * HID + j];
        }
    }
    int pn = p + nb_c;

    while (nb_c > 0) {
        // prefetch next batch
        int nb_n = min(4, pe - pn);
        float xl_nx[4]; float2 ea_nx[4];
        #pragma unroll
        for (int q = 0; q < 4; q++) {
            if (q < nb_n) {
                int s = d_csrc[pn + q];
                ea_nx[q] = d_cea[pn + q];
                xl_nx[q] = d_xl[(size_t)s * HID + j];
            }
        }
        // scores for current batch
        float tt[4];
        #pragma unroll
        for (int q = 0; q < 4; q++) {
            if (q < nb_c) {
                float mm = xl_c[q] + xr_j + ea_c[q].x * w0 + ea_c[q].y * w1;
                mm = mm > 0.f ? mm : 0.2f * mm;
                tt[q] = mm * aj;
            } else {
                tt[q] = -1e30f;
                xl_c[q] = 0.f;
            }
        }
        // interleaved 16-lane reductions
        #pragma unroll
        for (int o = 8; o; o >>= 1) {
            #pragma unroll
            for (int q = 0; q < 4; q++)
                tt[q] += __shfl_xor_sync(0xffffffffu, tt[q], o);
        }
        // combined online-softmax merge
        float nm = run_m;
        #pragma unroll
        for (int q = 0; q < 4; q++) nm = fmaxf(nm, tt[q]);
        float sc = __expf(run_m - nm);
        float e0 = __expf(tt[0] - nm);
        float e1 = __expf(tt[1] - nm);
        float e2 = __expf(tt[2] - nm);
        float e3 = __expf(tt[3] - nm);
        den = den * sc + (e0 + e1) + (e2 + e3);
        acc = acc * sc + (e0 * xl_c[0] + e1 * xl_c[1]) + (e2 * xl_c[2] + e3 * xl_c[3]);
        run_m = nm;
        // advance
        nb_c = nb_n;
        pn += nb_n;
        #pragma unroll
        for (int q = 0; q < 4; q++) { xl_c[q] = xl_nx[q]; ea_c[q] = ea_nx[q]; }
    }

    float v = d_h[(size_t)n * HID + j] + acc / den + bo[j];
    float mean, rstd; blockStats192(v, mean, rstd);
    d_h[(size_t)n * HID + j] = (v - mean) * rstd * g[j] + b[j];
}

// ---------------- gate: d_tmp = h * sigmoid(h@Wg + bg) ----------------
__global__ void k_gate(const float* __restrict__ Wg, const float* __restrict__ bg) {
    __shared__ float sh[TM * HID];
    int base = blockIdx.x * TM;
    int j = threadIdx.x;
    {
        const float4* src = (const float4*)&d_h[(size_t)base * HID];
        float4* dstv = (float4*)sh;
        for (int i = j; i < TM * HID / 4; i += HID) dstv[i] = src[i];
    }
    __syncthreads();
    u64t acc2[TM];
    #pragma unroll
    for (int m = 0; m < TM; m++) acc2[m] = 0ull;
    for (int k = 0; k < HID; k += 4) {
        float w0 = Wg[(k + 0) * HID + j], w1 = Wg[(k + 1) * HID + j];
        float w2 = Wg[(k + 2) * HID + j], w3 = Wg[(k + 3) * HID + j];
        u64t wp01 = pack2(w0, w1), wp23 = pack2(w2, w3);
        #pragma unroll
        for (int m = 0; m < TM; m++) {
            ulonglong2 hp = *(const ulonglong2*)&sh[m * HID + k];
            ffma2(acc2[m], hp.x, wp01);
            ffma2(acc2[m], hp.y, wp23);
        }
    }
    float bj = bg[j];
    #pragma unroll
    for (int m = 0; m < TM; m++) {
        float gsig = 1.f / (1.f + __expf(-(unpack_sum(acc2[m]) + bj)));
        d_tmp[(size_t)(base + m) * HID + j] = sh[m * HID + j] * gsig;
    }
}

// ---------------- launcher ----------------
extern "C" void kernel_launch(void* const* d_in, const int* in_sizes, int n_in,
                              void* d_out, int out_size) {
    const float* x     = (const float*)d_in[0];
    const int*   ei    = (const int*)  d_in[1];
    const float* eattr = (const float*)d_in[2];
    const float* Win   = (const float*)d_in[3];
    const float* b_in  = (const float*)d_in[4];
    const float* g_lni = (const float*)d_in[5];
    const float* b_lni = (const float*)d_in[6];
    const float* Wl    = (const float*)d_in[7];
    const float* bl    = (const float*)d_in[8];
    const float* Wr    = (const float*)d_in[9];
    const float* br    = (const float*)d_in[10];
    const float* We    = (const float*)d_in[11];
    const float* att   = (const float*)d_in[12];
    const float* bo    = (const float*)d_in[13];
    const float* g_res = (const float*)d_in[14];
    const float* b_res = (const float*)d_in[15];
    const float* Wg    = (const float*)d_in[16];
    const float* bg    = (const float*)d_in[17];
    const float* g_f   = (const float*)d_in[18];
    const float* b_f   = (const float*)d_in[19];
    float* out = (float*)d_out;

    float *p_tmp, *p_h;
    cudaGetSymbolAddress((void**)&p_tmp, d_tmp);
    cudaGetSymbolAddress((void**)&p_h,   d_h);

    // CSR build + self-loop mean edge_attr
    k_zero<<<(2 * NN + 255) / 256, 256>>>();
    k_hist<<<(NE + 255) / 256, 256>>>(ei, eattr);
    k_mean<<<(NN + 255) / 256, 256>>>();
    k_scanA<<<NB, 1024>>>();
    k_scanB<<<1, 64>>>();
    k_scanC<<<NB, 1024>>>();
    k_scatter<<<(NE + 255) / 256, 256>>>(ei, eattr);

    // input projection + GELU + LN -> d_h
    k_inproj<<<NN / TM, HID>>>(x, Win, b_in);
    k_ln<<<NN, HID>>>(p_tmp, g_lni, b_lni, p_h);

    for (int l = 0; l < NL; l++) {
        k_gemm2<<<NN / TG, HID>>>(Wl + (size_t)l * HID * HID, bl + l * HID,
                                  Wr + (size_t)l * HID * HID, br + l * HID);
        k_node<<<NN, HID>>>(We + (size_t)l * 2 * HID, att + (size_t)l * HID,
                            bo + l * HID, g_res + l * HID, b_res + l * HID);
    }

    k_gate<<<NN / TM, HID>>>(Wg, bg);
    k_ln<<<NN, HID>>>(p_tmp, g_f, b_f, out);
}